// round 7
// baseline (speedup 1.0000x reference)
#include <cuda_runtime.h>
#include <cstdint>

/*
 Top-K mask of zero-diagonal outer(p,p), N=8192, K=262144.
 k_select (1 block, 1024 thr, 128KB smem):
   - counting sort of p fully in shared (16384-bin hi-14-key hist + per-run fix)
   - exact bisection over uint32 sortable-key space; per-thread STAIRCASE
     counting: one warm-started anchor search + monotone walk across the
     thread's 8 contiguous sorted rows (cross-row boundary monotonicity)
   - exact tie budget + smallest-flat-index cut (jax top_k stability)
 k_out: fused 268MB float4 streaming-store pass (store-roofline bound).
*/

#define N      8192
#define KTOP   262144u
#define NBINS  16384
#define KSHIFT 18
#define TIECAP 4096

__device__ float    g_thr;
__device__ unsigned g_cut;

__device__ __forceinline__ unsigned fkey(float f) {
    unsigned u = __float_as_uint(f);
    return u ^ (((unsigned)((int)u >> 31)) | 0x80000000u);
}
__device__ __forceinline__ float unflip(unsigned k) {
    unsigned u = (k & 0x80000000u) ? (k ^ 0x80000000u) : ~k;
    return __uint_as_float(u);
}

/* boundary b in [lo0,hi0] (predicate monotone over whole array for T>0):
   v>0: pred(m)=(v*s[m]>=T) true for m<b ; count = b
   v<0: pred(m)=(v*s[m]>=T) true for m>=b; count = N-b */
__device__ __forceinline__ int bs_bound(float v, float T, const float* s,
                                        int lo0, int hi0) {
    int lo = lo0, hi = hi0;
    if (v > 0.0f) {
        while (lo < hi) { int m = (lo + hi) >> 1; if (v * s[m] >= T) lo = m + 1; else hi = m; }
    } else {
        while (lo < hi) { int m = (lo + hi) >> 1; if (v * s[m] >= T) hi = m; else lo = m + 1; }
    }
    return lo;
}

__global__ void k_select(const float* __restrict__ p) {
    extern __shared__ unsigned char sm[];
    unsigned* s_off = (unsigned*)sm;                 /* [16384] 64KB; later tie buf */
    float*    s_val = (float*)(sm + 65536);          /* [8192] 32KB */
    int*      s_idx = (int*)(sm + 98304);            /* [8192] 32KB */
    unsigned* s_tie = s_off;
    __shared__ unsigned cur[1024];
    __shared__ unsigned s_red[32];
    __shared__ unsigned s_lo, s_hi, s_dec, s_total, s_ntie, s_cut;

    const int t = threadIdx.x;   /* 1024 threads */

    for (int i = t; i < NBINS; i += 1024) s_off[i] = 0u;
    __syncthreads();

    /* ---- hist (hi-14 key) ---- */
    float pv[8];
    #pragma unroll
    for (int j = 0; j < 8; j++) {
        pv[j] = p[t + j * 1024];
        atomicAdd(&s_off[fkey(pv[j]) >> KSHIFT], 1u);
    }
    __syncthreads();

    /* ---- suffix scan -> s_off[b] = #keys in bins strictly above b ---- */
    {
        const int base = t * 16;
        unsigned h[16]; unsigned ct = 0;
        #pragma unroll
        for (int j = 0; j < 16; j++) { h[j] = s_off[base + j]; ct += h[j]; }
        cur[t] = ct; __syncthreads();
        for (int d = 1; d < 1024; d <<= 1) {
            unsigned v2 = cur[t] + ((t + d < 1024) ? cur[t + d] : 0u);
            __syncthreads(); cur[t] = v2; __syncthreads();
        }
        unsigned g = cur[t] - ct;
        for (int j = 15; j >= 0; j--) {
            s_off[base + j] = g;
            g += h[j];
        }
    }
    __syncthreads();

    /* ---- scatter (descending by bin) ---- */
    #pragma unroll
    for (int j = 0; j < 8; j++) {
        unsigned b = fkey(pv[j]) >> KSHIFT;
        unsigned pos = atomicAdd(&s_off[b], 1u);
        s_val[pos] = pv[j];
        s_idx[pos] = t + j * 1024;
    }
    __syncthreads();

    /* ---- per-run insertion fix ---- */
    for (int i = t; i < N; i += 1024) {
        unsigned bi = fkey(s_val[i]) >> KSHIFT;
        if (i > 0 && (fkey(s_val[i - 1]) >> KSHIFT) == bi) continue;
        int e = i + 1;
        while (e < N && (fkey(s_val[e]) >> KSHIFT) == bi) e++;
        for (int a = i + 1; a < e; a++) {
            float kv = s_val[a]; int ki = s_idx[a];
            int j = a - 1;
            while (j >= i && s_val[j] < kv) {
                s_val[j + 1] = s_val[j]; s_idx[j + 1] = s_idx[j]; j--;
            }
            s_val[j + 1] = kv; s_idx[j + 1] = ki;
        }
    }
    __syncthreads();

    /* contiguous rows for this thread */
    float rv[8];
    #pragma unroll
    for (int j = 0; j < 8; j++) rv[j] = s_val[8 * t + j];

    /* warm-start interval for the FIRST row's anchor only (sign-aware).
       v>0: boundary decreasing in T ; v<0: boundary increasing in T. */
    int bmin0 = 0, bmax0 = N;
    if (t == 0) { s_lo = 0x80000000u; s_hi = 0xFFFFFFFFu; }
    __syncthreads();

    for (;;) {
        unsigned lo = s_lo, hi = s_hi;
        if (hi - lo <= 1u) break;
        unsigned mid = lo + ((hi - lo) >> 1);
        float T = unflip(mid);   /* always > 0 */

        unsigned c = 0;
        int b = 0, bm0 = -1;
        float prevv = 0.0f; bool have = false;
        #pragma unroll
        for (int j = 0; j < 8; j++) {
            float v = rv[j];
            if (v == 0.0f) { have = false; continue; }
            bool ps = (v > 0.0f);
            if (j == 0) {
                b = bs_bound(v, T, s_val, bmin0, bmax0);
                bm0 = b;
            } else if (!have || (ps != (prevv > 0.0f))) {
                b = bs_bound(v, T, s_val, 0, N);
            } else {
                /* monotone walk down (both signs) from previous row's boundary */
                if (ps) { while (b > 0 && !(v * s_val[b - 1] >= T)) b--; }
                else    { while (b > 0 &&  (v * s_val[b - 1] >= T)) b--; }
            }
            have = true; prevv = v;
            unsigned cj = ps ? (unsigned)b : (unsigned)(N - b);
            if (v * v >= T) cj -= 1u;   /* drop diagonal */
            c += cj;
        }
        #pragma unroll
        for (int d = 16; d > 0; d >>= 1) c += __shfl_down_sync(0xffffffffu, c, d);
        if ((t & 31) == 0) s_red[t >> 5] = c;
        __syncthreads();
        if (t < 32) {
            unsigned x = s_red[t];
            #pragma unroll
            for (int d = 16; d > 0; d >>= 1) x += __shfl_down_sync(0xffffffffu, x, d);
            if (t == 0) {
                if (x >= KTOP) { s_lo = mid; s_dec = 1u; }
                else           { s_hi = mid; s_dec = 0u; }
            }
        }
        __syncthreads();
        if (bm0 >= 0) {
            bool ps0 = (rv[0] > 0.0f);
            if (s_dec) { if (ps0) bmax0 = bm0; else bmin0 = bm0; }
            else       { if (ps0) bmin0 = bm0; else bmax0 = bm0; }
        }
    }
    const unsigned Tk = s_lo;
    const float thr  = unflip(Tk);
    const float thr1 = unflip(Tk + 1u);

    /* ---- strict-above count at thr1 -> tie budget r ---- */
    {
        unsigned c = 0;
        int b = 0; float prevv = 0.0f; bool have = false;
        #pragma unroll
        for (int j = 0; j < 8; j++) {
            float v = rv[j];
            if (v == 0.0f) { have = false; continue; }
            bool ps = (v > 0.0f);
            if (!have || (ps != (prevv > 0.0f))) {
                b = bs_bound(v, thr1, s_val, 0, N);
            } else {
                if (ps) { while (b > 0 && !(v * s_val[b - 1] >= thr1)) b--; }
                else    { while (b > 0 &&  (v * s_val[b - 1] >= thr1)) b--; }
            }
            have = true; prevv = v;
            unsigned cj = ps ? (unsigned)b : (unsigned)(N - b);
            if (v * v >= thr1) cj -= 1u;
            c += cj;
        }
        #pragma unroll
        for (int d = 16; d > 0; d >>= 1) c += __shfl_down_sync(0xffffffffu, c, d);
        if ((t & 31) == 0) s_red[t >> 5] = c;
        __syncthreads();
        if (t < 32) {
            unsigned x = s_red[t];
            #pragma unroll
            for (int d = 16; d > 0; d >>= 1) x += __shfl_down_sync(0xffffffffu, x, d);
            if (t == 0) { s_total = x; s_ntie = 0; }
        }
        __syncthreads();
    }
    const unsigned r = KTOP - s_total;

    /* ---- collect tie pairs (value == thr), skip diagonal ---- */
    #pragma unroll
    for (int j = 0; j < 8; j++) {
        int row = 8 * t + j;
        float v = rv[j];
        if (v == 0.0f) continue;
        int bA = bs_bound(v, thr,  s_val, 0, N);
        int bB = bs_bound(v, thr1, s_val, 0, N);
        int m0, m1;
        if (v > 0.0f) { m0 = bB; m1 = bA; } else { m0 = bA; m1 = bB; }
        if (m1 <= m0) continue;
        unsigned fb = ((unsigned)s_idx[row]) << 13;
        for (int m = m0; m < m1; m++) {
            if (m == row) continue;
            unsigned pos = atomicAdd(&s_ntie, 1u);
            if (pos < TIECAP) s_tie[pos] = fb + (unsigned)s_idx[m];
        }
    }
    __syncthreads();

    /* ---- cut = tie flat with rank r ---- */
    unsigned nt = min(s_ntie, (unsigned)TIECAP);
    if (t == 0) s_cut = (r >= nt) ? 0xFFFFFFFFu : 0u;
    __syncthreads();
    if (r < nt) {
        for (unsigned i = t; i < nt; i += 1024) {
            unsigned x = s_tie[i];
            unsigned rk = 0;
            for (unsigned j2 = 0; j2 < nt; j2++) rk += (s_tie[j2] < x) ? 1u : 0u;
            if (rk == r) s_cut = x;
        }
    }
    __syncthreads();
    if (t == 0) { g_thr = thr; g_cut = s_cut; }
}

/* ---- fused output pass ---- */
__device__ __forceinline__ float edgev(float v, float thr, unsigned flat, unsigned cut, bool diag) {
    bool ok = ((v > thr) | ((v == thr) & (flat < cut))) & (!diag);
    return ok ? 1.0f : 0.0f;
}

__global__ void k_out(const float* __restrict__ p, float4* __restrict__ out) {
    int row = blockIdx.y;
    float pi = __ldg(p + row);
    float thr = g_thr;
    unsigned cut = g_cut;
    const float4* __restrict__ q4 = (const float4*)p;
    int f0 = blockIdx.x * 1024 + threadIdx.x;
    unsigned fbase = ((unsigned)row) << 13;
    unsigned outrow = ((unsigned)row) << 11;
    #pragma unroll
    for (int k = 0; k < 4; k++) {
        int f = f0 + k * 256;
        float4 q = __ldg(q4 + f);
        unsigned j0 = ((unsigned)f) << 2;
        float4 o;
        o.x = edgev(pi * q.x, thr, fbase + j0 + 0u, cut, (j0 + 0u) == (unsigned)row);
        o.y = edgev(pi * q.y, thr, fbase + j0 + 1u, cut, (j0 + 1u) == (unsigned)row);
        o.z = edgev(pi * q.z, thr, fbase + j0 + 2u, cut, (j0 + 2u) == (unsigned)row);
        o.w = edgev(pi * q.w, thr, fbase + j0 + 3u, cut, (j0 + 3u) == (unsigned)row);
        __stcs(out + outrow + (unsigned)f, o);   /* streaming store */
    }
}

extern "C" void kernel_launch(void* const* d_in, const int* in_sizes, int n_in,
                              void* d_out, int out_size) {
    const float* p = (const float*)d_in[0];
    float* out = (float*)d_out;
    (void)in_sizes; (void)n_in; (void)out_size;

    const int SMEM = 65536 + 32768 + 32768;   /* 131072 B dynamic */
    cudaFuncSetAttribute(k_select, cudaFuncAttributeMaxDynamicSharedMemorySize, SMEM);

    k_select<<<1, 1024, SMEM>>>(p);

    dim3 grid(2, N);
    k_out<<<grid, 256>>>(p, (float4*)out);
}

// round 9
// speedup vs baseline: 2.1512x; 2.1512x over previous
#include <cuda_runtime.h>
#include <cstdint>

/*
 Top-K mask of zero-diagonal outer(p,p), N=8192, K=262144.
 k_select (1 block, 1024 thr, 128KB smem, __launch_bounds__(1024,1)):
   - counting sort of p fully in shared (16384-bin hi-14-key hist + per-run fix)
   - exact bisection over uint32 sortable-key space; per-thread LOCKSTEP
     searches over its 8 contiguous sorted rows (8 independent LDS chains, ILP)
   - same-sign search ranges + per-row warm-start intervals PACKED 16+16 bit
   - exact tie budget + smallest-flat-index cut (jax top_k stability)
 k_out: fused 268MB float4 streaming-store pass (store-roofline bound).
*/

#define N      8192
#define KTOP   262144u
#define NBINS  16384
#define KSHIFT 18
#define TIECAP 4096

__device__ float    g_thr;
__device__ unsigned g_cut;

__device__ __forceinline__ unsigned fkey(float f) {
    unsigned u = __float_as_uint(f);
    return u ^ (((unsigned)((int)u >> 31)) | 0x80000000u);
}
__device__ __forceinline__ float unflip(unsigned k) {
    unsigned u = (k & 0x80000000u) ? (k ^ 0x80000000u) : ~k;
    return __uint_as_float(u);
}

/* single-row boundary search in [lo0,hi0]:
   v>0: pred(m)=(v*s[m]>=T) true for m<b ; v<0: pred true for m>=b */
__device__ __forceinline__ int bs_bound(float v, float T, const float* s,
                                        int lo0, int hi0) {
    int lo = lo0, hi = hi0;
    if (v > 0.0f) {
        while (lo < hi) { int m = (lo + hi) >> 1; if (v * s[m] >= T) lo = m + 1; else hi = m; }
    } else {
        while (lo < hi) { int m = (lo + hi) >> 1; if (v * s[m] >= T) hi = m; else lo = m + 1; }
    }
    return lo;
}

__global__ void __launch_bounds__(1024, 1) k_select(const float* __restrict__ p) {
    extern __shared__ unsigned char sm[];
    unsigned* s_off = (unsigned*)sm;                 /* [16384] 64KB; later tie buf */
    float*    s_val = (float*)(sm + 65536);          /* [8192] 32KB */
    int*      s_idx = (int*)(sm + 98304);            /* [8192] 32KB */
    unsigned* s_tie = s_off;
    __shared__ unsigned cur[1024];
    __shared__ unsigned s_red[32];
    __shared__ unsigned s_lo, s_hi, s_dec, s_total, s_ntie, s_cut;
    __shared__ unsigned s_npos, s_nneg;

    const int t = threadIdx.x;   /* 1024 threads */

    for (int i = t; i < NBINS; i += 1024) s_off[i] = 0u;
    if (t == 0) { s_npos = 0; s_nneg = 0; }
    __syncthreads();

    /* ---- hist (hi-14 key) + sign counts ---- */
    float pv[8];
    unsigned cp = 0, cn = 0;
    #pragma unroll
    for (int j = 0; j < 8; j++) {
        pv[j] = p[t + j * 1024];
        atomicAdd(&s_off[fkey(pv[j]) >> KSHIFT], 1u);
        cp += (pv[j] > 0.0f); cn += (pv[j] < 0.0f);
    }
    atomicAdd(&s_npos, cp); atomicAdd(&s_nneg, cn);
    __syncthreads();

    /* ---- suffix scan -> s_off[b] = #keys in bins strictly above b ---- */
    {
        const int base = t * 16;
        unsigned h[16]; unsigned ct = 0;
        #pragma unroll
        for (int j = 0; j < 16; j++) { h[j] = s_off[base + j]; ct += h[j]; }
        cur[t] = ct; __syncthreads();
        for (int d = 1; d < 1024; d <<= 1) {
            unsigned v2 = cur[t] + ((t + d < 1024) ? cur[t + d] : 0u);
            __syncthreads(); cur[t] = v2; __syncthreads();
        }
        unsigned g = cur[t] - ct;
        for (int j = 15; j >= 0; j--) {
            s_off[base + j] = g;
            g += h[j];
        }
    }
    __syncthreads();

    /* ---- scatter (descending by bin) ---- */
    #pragma unroll
    for (int j = 0; j < 8; j++) {
        unsigned b = fkey(pv[j]) >> KSHIFT;
        unsigned pos = atomicAdd(&s_off[b], 1u);
        s_val[pos] = pv[j];
        s_idx[pos] = t + j * 1024;
    }
    __syncthreads();

    /* ---- per-run insertion fix ---- */
    for (int i = t; i < N; i += 1024) {
        unsigned bi = fkey(s_val[i]) >> KSHIFT;
        if (i > 0 && (fkey(s_val[i - 1]) >> KSHIFT) == bi) continue;
        int e = i + 1;
        while (e < N && (fkey(s_val[e]) >> KSHIFT) == bi) e++;
        for (int a = i + 1; a < e; a++) {
            float kv = s_val[a]; int ki = s_idx[a];
            int j = a - 1;
            while (j >= i && s_val[j] < kv) {
                s_val[j + 1] = s_val[j]; s_idx[j + 1] = s_idx[j]; j--;
            }
            s_val[j + 1] = kv; s_idx[j + 1] = ki;
        }
    }
    __syncthreads();

    const int P = (int)s_npos;        /* positives occupy [0,P)   */
    const int Z = N - (int)s_nneg;    /* negatives occupy [Z,N)   */

    /* contiguous rows for this thread */
    float rv[8];
    #pragma unroll
    for (int j = 0; j < 8; j++) rv[j] = s_val[8 * t + j];

    /* packed warm-start intervals: low16 = bmin, high16 = bmax (class range) */
    unsigned bw[8];
    #pragma unroll
    for (int j = 0; j < 8; j++) {
        int c0, c1;
        if (rv[j] > 0.0f)      { c0 = 0; c1 = P; }
        else if (rv[j] < 0.0f) { c0 = Z; c1 = N; }
        else                   { c0 = 0; c1 = 0; }
        bw[j] = (unsigned)c0 | ((unsigned)c1 << 16);
    }

    if (t == 0) { s_lo = 0x80000000u; s_hi = 0xFFFFFFFFu; }
    __syncthreads();

    for (;;) {
        unsigned klo = s_lo, khi = s_hi;
        if (khi - klo <= 1u) break;
        unsigned mid = klo + ((khi - klo) >> 1);
        float T = unflip(mid);   /* > 0 */

        /* ---- lockstep 8-row boundary search (independent chains = ILP) ---- */
        int lo[8], hi[8];
        #pragma unroll
        for (int j = 0; j < 8; j++) { lo[j] = (int)(bw[j] & 0xFFFFu); hi[j] = (int)(bw[j] >> 16); }
        bool any = true;
        while (any) {
            any = false;
            #pragma unroll
            for (int j = 0; j < 8; j++) {
                if (lo[j] < hi[j]) {
                    int m = (lo[j] + hi[j]) >> 1;
                    float sv = s_val[m];
                    bool pred = (rv[j] * sv >= T);
                    bool up = (rv[j] > 0.0f) ? pred : !pred;
                    if (up) lo[j] = m + 1; else hi[j] = m;
                    any |= (lo[j] < hi[j]);
                }
            }
        }

        unsigned c = 0;
        #pragma unroll
        for (int j = 0; j < 8; j++) {
            float v = rv[j];
            if (v == 0.0f) continue;
            unsigned cj = (v > 0.0f) ? (unsigned)lo[j] : (unsigned)(N - lo[j]);
            if (v * v >= T) cj -= 1u;     /* drop diagonal */
            c += cj;
        }
        #pragma unroll
        for (int d = 16; d > 0; d >>= 1) c += __shfl_down_sync(0xffffffffu, c, d);
        if ((t & 31) == 0) s_red[t >> 5] = c;
        __syncthreads();
        if (t < 32) {
            unsigned x = s_red[t];
            #pragma unroll
            for (int d = 16; d > 0; d >>= 1) x += __shfl_down_sync(0xffffffffu, x, d);
            if (t == 0) {
                if (x >= KTOP) { s_lo = mid; s_dec = 1u; }
                else           { s_hi = mid; s_dec = 0u; }
            }
        }
        __syncthreads();
        unsigned dec = s_dec;
        #pragma unroll
        for (int j = 0; j < 8; j++) {
            float v = rv[j];
            if (v == 0.0f) continue;
            unsigned b = (unsigned)lo[j];
            unsigned bmn = bw[j] & 0xFFFFu, bmx = bw[j] >> 16;
            if (dec) { if (v > 0.0f) bmx = b; else bmn = b; }   /* T in (mid,khi] */
            else     { if (v > 0.0f) bmn = b; else bmx = b; }   /* T in [klo,mid) */
            bw[j] = bmn | (bmx << 16);
        }
    }
    const unsigned Tk = s_lo;
    const float thr  = unflip(Tk);
    const float thr1 = unflip(Tk + 1u);

    /* ---- strict-above count at thr1 (lockstep, warm ranges) -> tie budget ---- */
    {
        int lo[8], hi[8];
        #pragma unroll
        for (int j = 0; j < 8; j++) { lo[j] = (int)(bw[j] & 0xFFFFu); hi[j] = (int)(bw[j] >> 16); }
        bool any = true;
        while (any) {
            any = false;
            #pragma unroll
            for (int j = 0; j < 8; j++) {
                if (lo[j] < hi[j]) {
                    int m = (lo[j] + hi[j]) >> 1;
                    float sv = s_val[m];
                    bool pred = (rv[j] * sv >= thr1);
                    bool up = (rv[j] > 0.0f) ? pred : !pred;
                    if (up) lo[j] = m + 1; else hi[j] = m;
                    any |= (lo[j] < hi[j]);
                }
            }
        }
        unsigned c = 0;
        #pragma unroll
        for (int j = 0; j < 8; j++) {
            float v = rv[j];
            if (v == 0.0f) continue;
            unsigned cj = (v > 0.0f) ? (unsigned)lo[j] : (unsigned)(N - lo[j]);
            if (v * v >= thr1) cj -= 1u;
            c += cj;
        }
        #pragma unroll
        for (int d = 16; d > 0; d >>= 1) c += __shfl_down_sync(0xffffffffu, c, d);
        if ((t & 31) == 0) s_red[t >> 5] = c;
        __syncthreads();
        if (t < 32) {
            unsigned x = s_red[t];
            #pragma unroll
            for (int d = 16; d > 0; d >>= 1) x += __shfl_down_sync(0xffffffffu, x, d);
            if (t == 0) { s_total = x; s_ntie = 0; }
        }
        __syncthreads();
    }
    const unsigned r = KTOP - s_total;

    /* ---- collect tie pairs (product == thr), skip diagonal ---- */
    #pragma unroll
    for (int j = 0; j < 8; j++) {
        int row = 8 * t + j;
        float v = rv[j];
        if (v == 0.0f) continue;
        int c0, c1;
        if (v > 0.0f) { c0 = 0; c1 = P; } else { c0 = Z; c1 = N; }
        int bA = bs_bound(v, thr,  s_val, c0, c1);
        int bB = bs_bound(v, thr1, s_val, c0, c1);
        int m0, m1;
        if (v > 0.0f) { m0 = bB; m1 = bA; } else { m0 = bA; m1 = bB; }
        if (m1 <= m0) continue;
        unsigned fb = ((unsigned)s_idx[row]) << 13;
        for (int m = m0; m < m1; m++) {
            if (m == row) continue;
            unsigned pos = atomicAdd(&s_ntie, 1u);
            if (pos < TIECAP) s_tie[pos] = fb + (unsigned)s_idx[m];
        }
    }
    __syncthreads();

    /* ---- cut = tie flat with rank r ---- */
    unsigned nt = min(s_ntie, (unsigned)TIECAP);
    if (t == 0) s_cut = (r >= nt) ? 0xFFFFFFFFu : 0u;
    __syncthreads();
    if (r < nt) {
        for (unsigned i = t; i < nt; i += 1024) {
            unsigned x = s_tie[i];
            unsigned rk = 0;
            for (unsigned j2 = 0; j2 < nt; j2++) rk += (s_tie[j2] < x) ? 1u : 0u;
            if (rk == r) s_cut = x;
        }
    }
    __syncthreads();
    if (t == 0) { g_thr = thr; g_cut = s_cut; }
}

/* ---- fused output pass ---- */
__device__ __forceinline__ float edgev(float v, float thr, unsigned flat, unsigned cut, bool diag) {
    bool ok = ((v > thr) | ((v == thr) & (flat < cut))) & (!diag);
    return ok ? 1.0f : 0.0f;
}

__global__ void k_out(const float* __restrict__ p, float4* __restrict__ out) {
    int row = blockIdx.y;
    float pi = __ldg(p + row);
    float thr = g_thr;
    unsigned cut = g_cut;
    const float4* __restrict__ q4 = (const float4*)p;
    int f0 = blockIdx.x * 1024 + threadIdx.x;
    unsigned fbase = ((unsigned)row) << 13;
    unsigned outrow = ((unsigned)row) << 11;
    #pragma unroll
    for (int k = 0; k < 4; k++) {
        int f = f0 + k * 256;
        float4 q = __ldg(q4 + f);
        unsigned j0 = ((unsigned)f) << 2;
        float4 o;
        o.x = edgev(pi * q.x, thr, fbase + j0 + 0u, cut, (j0 + 0u) == (unsigned)row);
        o.y = edgev(pi * q.y, thr, fbase + j0 + 1u, cut, (j0 + 1u) == (unsigned)row);
        o.z = edgev(pi * q.z, thr, fbase + j0 + 2u, cut, (j0 + 2u) == (unsigned)row);
        o.w = edgev(pi * q.w, thr, fbase + j0 + 3u, cut, (j0 + 3u) == (unsigned)row);
        __stcs(out + outrow + (unsigned)f, o);
    }
}

extern "C" void kernel_launch(void* const* d_in, const int* in_sizes, int n_in,
                              void* d_out, int out_size) {
    const float* p = (const float*)d_in[0];
    float* out = (float*)d_out;
    (void)in_sizes; (void)n_in; (void)out_size;

    const int SMEM = 65536 + 32768 + 32768;   /* 131072 B dynamic */
    cudaFuncSetAttribute(k_select, cudaFuncAttributeMaxDynamicSharedMemorySize, SMEM);

    k_select<<<1, 1024, SMEM>>>(p);

    dim3 grid(2, N);
    k_out<<<grid, 256>>>(p, (float4*)out);
}

// round 11
// speedup vs baseline: 2.7275x; 1.2679x over previous
#include <cuda_runtime.h>
#include <cstdint>

/*
 Top-K mask of zero-diagonal outer(p,p), N=8192, K=262144.
 Distributed radix-style selection:
   k_sort  (1 block): on-chip counting sort of p -> g_sval/g_sidx
   k_count (256 blocks x2 levels): exact count(>=edge) at 256 key-space edges
           via per-row 14-step guarded binary search on sorted p (L1-resident)
   k_n1/k_n2 (tiny): pick bracketing pair of edges around rank K
   k_enum  (32 blocks): emit (key,flat) for all products inside final bracket
   k_exact (1 block): exact K-th key + tie budget + smallest-flat-index cut
   k_out   : fused 268MB float4 streaming-store pass (store-roofline bound)
*/

#define N      8192
#define KTOP   262144u
#define NBINS  16384
#define KSHIFT 18
#define TIECAP 4096
#define CAP    (1u<<20)

__device__ float    g_sval[N];
__device__ int      g_sidx[N];
__device__ unsigned g_cnt1[257];
__device__ unsigned g_cnt2[257];
__device__ unsigned g_lo1, g_hi1, g_chi1;
__device__ unsigned g_lo2, g_hi2, g_chi2;
__device__ unsigned g_keys[CAP];
__device__ unsigned g_flats[CAP];
__device__ unsigned g_m;
__device__ float    g_thr;
__device__ unsigned g_cut;

__device__ __forceinline__ unsigned fkey(float f) {
    unsigned u = __float_as_uint(f);
    return u ^ (((unsigned)((int)u >> 31)) | 0x80000000u);
}
__device__ __forceinline__ float unflip(unsigned k) {
    unsigned u = (k & 0x80000000u) ? (k ^ 0x80000000u) : ~k;
    return __uint_as_float(u);
}

/* boundary b in [0,N):
   v>0: pred(m)=(v*s[m]>=T) true for m<b ; count = b
   v<0: pred(m)=(v*s[m]>=T) true for m>=b; count = N-b */
__device__ __forceinline__ int bs_bound(float v, float T, const float* s) {
    int lo = 0, hi = N;
    if (v > 0.0f) {
        while (lo < hi) { int m = (lo + hi) >> 1; if (v * __ldg(s + m) >= T) lo = m + 1; else hi = m; }
    } else {
        while (lo < hi) { int m = (lo + hi) >> 1; if (v * __ldg(s + m) >= T) hi = m; else lo = m + 1; }
    }
    return lo;
}

/* ================= k_sort: validated on-chip counting sort ================= */
__global__ void __launch_bounds__(1024, 1) k_sort(const float* __restrict__ p) {
    extern __shared__ unsigned char sm[];
    unsigned* s_off = (unsigned*)sm;                 /* [16384] 64KB */
    float*    s_val = (float*)(sm + 65536);          /* [8192] 32KB */
    int*      s_idx = (int*)(sm + 98304);            /* [8192] 32KB */
    __shared__ unsigned cur[1024];

    const int t = threadIdx.x;

    for (int i = t; i < NBINS; i += 1024) s_off[i] = 0u;
    __syncthreads();

    float pv[8];
    #pragma unroll
    for (int j = 0; j < 8; j++) {
        pv[j] = p[t + j * 1024];
        atomicAdd(&s_off[fkey(pv[j]) >> KSHIFT], 1u);
    }
    __syncthreads();

    /* suffix scan: s_off[b] = #keys in bins strictly above b */
    {
        const int base = t * 16;
        unsigned h[16]; unsigned ct = 0;
        #pragma unroll
        for (int j = 0; j < 16; j++) { h[j] = s_off[base + j]; ct += h[j]; }
        cur[t] = ct; __syncthreads();
        for (int d = 1; d < 1024; d <<= 1) {
            unsigned v2 = cur[t] + ((t + d < 1024) ? cur[t + d] : 0u);
            __syncthreads(); cur[t] = v2; __syncthreads();
        }
        unsigned g = cur[t] - ct;
        for (int j = 15; j >= 0; j--) {
            s_off[base + j] = g;
            g += h[j];
        }
    }
    __syncthreads();

    #pragma unroll
    for (int j = 0; j < 8; j++) {
        unsigned b = fkey(pv[j]) >> KSHIFT;
        unsigned pos = atomicAdd(&s_off[b], 1u);
        s_val[pos] = pv[j];
        s_idx[pos] = t + j * 1024;
    }
    __syncthreads();

    /* per-run insertion fix (exact descending value order) */
    for (int i = t; i < N; i += 1024) {
        unsigned bi = fkey(s_val[i]) >> KSHIFT;
        if (i > 0 && (fkey(s_val[i - 1]) >> KSHIFT) == bi) continue;
        int e = i + 1;
        while (e < N && (fkey(s_val[e]) >> KSHIFT) == bi) e++;
        for (int a = i + 1; a < e; a++) {
            float kv = s_val[a]; int ki = s_idx[a];
            int j = a - 1;
            while (j >= i && s_val[j] < kv) {
                s_val[j + 1] = s_val[j]; s_idx[j + 1] = s_idx[j]; j--;
            }
            s_val[j + 1] = kv; s_idx[j + 1] = ki;
        }
    }
    __syncthreads();

    #pragma unroll
    for (int j = 0; j < 8; j++) {
        int i = t + j * 1024;
        g_sval[i] = s_val[i];
        g_sidx[i] = s_idx[i];
    }
    if (t < 257) { g_cnt1[t] = 0u; g_cnt2[t] = 0u; }
    if (t == 0) g_m = 0u;
}

/* ============ k_count: exact count(>=edge), one block per edge ============ */
__global__ void k_count(int level) {
    __shared__ unsigned red[32];
    const int e = blockIdx.x;          /* 0..255 */
    unsigned edge;
    if (level == 1) {
        edge = 0x80000000u + (unsigned)e * 0x800000u;
    } else {
        unsigned lo = g_lo1, w = g_hi1 - g_lo1;
        unsigned stride = w >> 8; if (!stride) stride = 1u;
        edge = lo + (unsigned)e * stride;
    }
    const float T = unflip(edge);
    const int t = threadIdx.x;         /* 256 */

    unsigned c = 0;
    for (int g = 0; g < 8; g++) {      /* 32 rows/thread, 4-row lockstep */
        int r0 = t + (g * 4) * 256;
        float v0 = __ldg(g_sval + r0);
        float v1 = __ldg(g_sval + r0 + 256);
        float v2 = __ldg(g_sval + r0 + 512);
        float v3 = __ldg(g_sval + r0 + 768);
        int lo0 = 0, hi0 = N, lo1 = 0, hi1 = N, lo2 = 0, hi2 = N, lo3 = 0, hi3 = N;
        #pragma unroll
        for (int s = 0; s < 14; s++) {    /* 14 guarded steps: range 8192 needs ceil(log2(8193)) */
            if (lo0 < hi0) { int m = (lo0 + hi0) >> 1; bool pr = (v0 * __ldg(g_sval + m) >= T);
                             if ((v0 > 0.0f) ? pr : !pr) lo0 = m + 1; else hi0 = m; }
            if (lo1 < hi1) { int m = (lo1 + hi1) >> 1; bool pr = (v1 * __ldg(g_sval + m) >= T);
                             if ((v1 > 0.0f) ? pr : !pr) lo1 = m + 1; else hi1 = m; }
            if (lo2 < hi2) { int m = (lo2 + hi2) >> 1; bool pr = (v2 * __ldg(g_sval + m) >= T);
                             if ((v2 > 0.0f) ? pr : !pr) lo2 = m + 1; else hi2 = m; }
            if (lo3 < hi3) { int m = (lo3 + hi3) >> 1; bool pr = (v3 * __ldg(g_sval + m) >= T);
                             if ((v3 > 0.0f) ? pr : !pr) lo3 = m + 1; else hi3 = m; }
        }
        if (v0 != 0.0f) { unsigned cj = (v0 > 0.0f) ? (unsigned)lo0 : (unsigned)(N - lo0); if (v0 * v0 >= T) cj--; c += cj; }
        if (v1 != 0.0f) { unsigned cj = (v1 > 0.0f) ? (unsigned)lo1 : (unsigned)(N - lo1); if (v1 * v1 >= T) cj--; c += cj; }
        if (v2 != 0.0f) { unsigned cj = (v2 > 0.0f) ? (unsigned)lo2 : (unsigned)(N - lo2); if (v2 * v2 >= T) cj--; c += cj; }
        if (v3 != 0.0f) { unsigned cj = (v3 > 0.0f) ? (unsigned)lo3 : (unsigned)(N - lo3); if (v3 * v3 >= T) cj--; c += cj; }
    }
    #pragma unroll
    for (int d = 16; d > 0; d >>= 1) c += __shfl_down_sync(0xffffffffu, c, d);
    if ((t & 31) == 0) red[t >> 5] = c;
    __syncthreads();
    if (t == 0) {
        unsigned s = 0;
        for (int i = 0; i < 8; i++) s += red[i];
        if (level == 1) g_cnt1[e] = s; else g_cnt2[e] = s;
    }
}

/* ============ k_n1 / k_n2: pick bracketing pair (tiny) ============ */
__global__ void k_n1() {
    if (threadIdx.x) return;
    int t1 = 0;
    for (int t = 255; t >= 0; t--) { if (g_cnt1[t] >= KTOP) { t1 = t; break; } }
    g_lo1 = 0x80000000u + (unsigned)t1 * 0x800000u;
    if (t1 < 255) { g_hi1 = 0x80000000u + (unsigned)(t1 + 1) * 0x800000u; g_chi1 = g_cnt1[t1 + 1]; }
    else          { g_hi1 = 0xFFFFFFFFu; g_chi1 = 0u; }
}
__global__ void k_n2() {
    if (threadIdx.x) return;
    unsigned lo = g_lo1, w = g_hi1 - g_lo1;
    unsigned stride = w >> 8; if (!stride) stride = 1u;
    int t2 = 0;
    for (int t = 255; t >= 0; t--) { if (g_cnt2[t] >= KTOP) { t2 = t; break; } }
    g_lo2 = lo + (unsigned)t2 * stride;
    if (t2 < 255) { g_hi2 = lo + (unsigned)(t2 + 1) * stride; g_chi2 = g_cnt2[t2 + 1]; }
    else          { g_hi2 = g_hi1; g_chi2 = g_chi1; }
}

/* ============ k_enum: emit candidates with key in [lo2, hi2) ============ */
__global__ void k_enum() {
    int row = blockIdx.x * 256 + threadIdx.x;
    float v = __ldg(g_sval + row);
    if (v == 0.0f) return;
    float TA = unflip(g_lo2);
    float TB = unflip(g_hi2);
    int bA = bs_bound(v, TA, g_sval);
    int bB = bs_bound(v, TB, g_sval);
    int m0, m1;
    if (v > 0.0f) { m0 = bB; m1 = bA; } else { m0 = bA; m1 = bB; }
    if (m1 <= m0) return;
    unsigned fb = ((unsigned)__ldg(g_sidx + row)) << 13;
    for (int m = m0; m < m1; m++) {
        if (m == row) continue;
        unsigned pos = atomicAdd(&g_m, 1u);
        if (pos < CAP) {
            g_keys[pos]  = fkey(v * __ldg(g_sval + m));
            g_flats[pos] = fb + (unsigned)__ldg(g_sidx + m);
        }
    }
}

/* ============ k_exact: exact K-th key + tie cut among M candidates ======= */
__global__ void __launch_bounds__(1024, 1) k_exact() {
    __shared__ unsigned hA[256];
    __shared__ unsigned hB[256];
    __shared__ unsigned s_tie[TIECAP];
    __shared__ unsigned s_ntie, s_binA, s_above, s_Tk, s_r, s_cut;

    const int t = threadIdx.x;
    const unsigned M = min(g_m, CAP);
    const unsigned lo2 = g_lo2, hi2 = g_hi2, chi = g_chi2;
    const unsigned w = hi2 - lo2;
    const unsigned binw = (w + 255u) >> 8;    /* level-A bin width, <=256 bins */

    if (t < 256) { hA[t] = 0u; hB[t] = 0u; }
    if (t == 0) s_ntie = 0u;
    __syncthreads();

    for (unsigned i = t; i < M; i += 1024)
        atomicAdd(&hA[(g_keys[i] - lo2) / binw], 1u);
    __syncthreads();

    if (t == 0) {
        unsigned acc = chi;
        int bA = 0;
        for (int b = 255; b >= 0; b--) {
            if (acc + hA[b] >= KTOP) { bA = b; break; }
            acc += hA[b];
        }
        s_binA = (unsigned)bA; s_above = acc;
    }
    __syncthreads();
    const unsigned binA = s_binA;
    const unsigned base = lo2 + binA * binw;

    for (unsigned i = t; i < M; i += 1024) {
        unsigned k = g_keys[i];
        if ((k - lo2) / binw == binA) atomicAdd(&hB[k - base], 1u);
    }
    __syncthreads();

    if (t == 0) {
        unsigned acc = s_above;
        unsigned off = 0;
        for (int o = (int)binw - 1; o >= 0; o--) {
            if (acc + hB[o] >= KTOP) { off = (unsigned)o; break; }
            acc += hB[o];
        }
        s_Tk = base + off;
        s_r = KTOP - acc;          /* #ties to include */
    }
    __syncthreads();
    const unsigned Tk = s_Tk, r = s_r;

    for (unsigned i = t; i < M; i += 1024) {
        if (g_keys[i] == Tk) {
            unsigned pos = atomicAdd(&s_ntie, 1u);
            if (pos < TIECAP) s_tie[pos] = g_flats[i];
        }
    }
    __syncthreads();

    unsigned nt = min(s_ntie, (unsigned)TIECAP);
    if (t == 0) s_cut = (r >= nt) ? 0xFFFFFFFFu : 0u;
    __syncthreads();
    if (r < nt) {
        for (unsigned i = t; i < nt; i += 1024) {
            unsigned x = s_tie[i];
            unsigned rk = 0;
            for (unsigned j = 0; j < nt; j++) rk += (s_tie[j] < x) ? 1u : 0u;
            if (rk == r) s_cut = x;
        }
    }
    __syncthreads();
    if (t == 0) { g_thr = unflip(Tk); g_cut = s_cut; }
}

/* ================= fused output pass (validated, roofline) ================ */
__device__ __forceinline__ float edgev(float v, float thr, unsigned flat, unsigned cut, bool diag) {
    bool ok = ((v > thr) | ((v == thr) & (flat < cut))) & (!diag);
    return ok ? 1.0f : 0.0f;
}

__global__ void k_out(const float* __restrict__ p, float4* __restrict__ out) {
    int row = blockIdx.y;
    float pi = __ldg(p + row);
    float thr = g_thr;
    unsigned cut = g_cut;
    const float4* __restrict__ q4 = (const float4*)p;
    int f0 = blockIdx.x * 1024 + threadIdx.x;
    unsigned fbase = ((unsigned)row) << 13;
    unsigned outrow = ((unsigned)row) << 11;
    #pragma unroll
    for (int k = 0; k < 4; k++) {
        int f = f0 + k * 256;
        float4 q = __ldg(q4 + f);
        unsigned j0 = ((unsigned)f) << 2;
        float4 o;
        o.x = edgev(pi * q.x, thr, fbase + j0 + 0u, cut, (j0 + 0u) == (unsigned)row);
        o.y = edgev(pi * q.y, thr, fbase + j0 + 1u, cut, (j0 + 1u) == (unsigned)row);
        o.z = edgev(pi * q.z, thr, fbase + j0 + 2u, cut, (j0 + 2u) == (unsigned)row);
        o.w = edgev(pi * q.w, thr, fbase + j0 + 3u, cut, (j0 + 3u) == (unsigned)row);
        __stcs(out + outrow + (unsigned)f, o);
    }
}

extern "C" void kernel_launch(void* const* d_in, const int* in_sizes, int n_in,
                              void* d_out, int out_size) {
    const float* p = (const float*)d_in[0];
    float* out = (float*)d_out;
    (void)in_sizes; (void)n_in; (void)out_size;

    const int SMEM = 65536 + 32768 + 32768;   /* 131072 B dynamic */
    cudaFuncSetAttribute(k_sort, cudaFuncAttributeMaxDynamicSharedMemorySize, SMEM);

    k_sort<<<1, 1024, SMEM>>>(p);
    k_count<<<256, 256>>>(1);
    k_n1<<<1, 32>>>();
    k_count<<<256, 256>>>(2);
    k_n2<<<1, 32>>>();
    k_enum<<<32, 256>>>();
    k_exact<<<1, 1024>>>();

    dim3 grid(2, N);
    k_out<<<grid, 256>>>(p, (float4*)out);
}